// round 13
// baseline (speedup 1.0000x reference)
#include <cuda_runtime.h>
#include <cuda_fp16.h>
#include <cstdint>

// Problem constants
#define NN 100000
#define EE 1600000
#define GGR 64

// ---------------- static device scratch (all intermediates fp16) ----------------
__device__ __half   g_q16 [(size_t)NN * 128];  // q, pre-scaled by 1/sqrt(128)
__device__ __half   g_kv16[(size_t)NN * 256];  // k[0:128) v[128:256)
__device__ __half   g_sk16[(size_t)NN * 128];  // skip connection
__device__ __half   g_h16 [(size_t)NN * 128];  // layer output
__device__ float    g_gate[NN];                // exp(gate logit)
__device__ float    g_pool[GGR * 128];
__device__ float    g_gs[GGR];
__device__ __half   g_Wh1[512 * 128];
__device__ __half   g_Wh2[512 * 128];
__device__ __half   g_Whg[128 * 128];
__device__ float    g_B1[512];
__device__ float    g_B2[512];
__device__ float    g_Bg[128];
// CSR (dst-sorted adjacency)
__device__ int      g_off[NN + 1];
__device__ int      g_cur[NN];
__device__ int      g_csrc[EE];
__device__ int      g_bsums[512];

#define QSCALE 0.08838834764831845f   // 1/sqrt(128)

// ---------------- fp16 mma ----------------
__device__ __forceinline__ void mma16(float* d, const uint32_t* a, const uint32_t* b) {
    asm volatile("mma.sync.aligned.m16n8k16.row.col.f32.f16.f16.f32 "
        "{%0,%1,%2,%3}, {%4,%5,%6,%7}, {%8,%9}, {%0,%1,%2,%3};"
        : "+f"(d[0]), "+f"(d[1]), "+f"(d[2]), "+f"(d[3])
        : "r"(a[0]), "r"(a[1]), "r"(a[2]), "r"(a[3]), "r"(b[0]), "r"(b[1]));
}

__device__ __forceinline__ void unpack8(const uint4& p, float* f) {
    float2 a = __half22float2(*(const __half2*)&p.x);
    float2 b = __half22float2(*(const __half2*)&p.y);
    float2 c = __half22float2(*(const __half2*)&p.z);
    float2 d = __half22float2(*(const __half2*)&p.w);
    f[0] = a.x; f[1] = a.y; f[2] = b.x; f[3] = b.y;
    f[4] = c.x; f[5] = c.y; f[6] = d.x; f[7] = d.y;
}

// ---------------- combined packing + graph init ----------------
__global__ void pack_all(const float* __restrict__ wq1, const float* __restrict__ bq1,
                         const float* __restrict__ wk1, const float* __restrict__ bk1,
                         const float* __restrict__ wv1, const float* __restrict__ bv1,
                         const float* __restrict__ ws1, const float* __restrict__ bs1,
                         const float* __restrict__ wq2, const float* __restrict__ bq2,
                         const float* __restrict__ wk2, const float* __restrict__ bk2,
                         const float* __restrict__ wv2, const float* __restrict__ bv2,
                         const float* __restrict__ ws2, const float* __restrict__ bs2,
                         const float* __restrict__ gw1, const float* __restrict__ gb1) {
    int idx = blockIdx.x * blockDim.x + threadIdx.x;
    if (idx < 512 * 128) {
        int orow = idx >> 7, k = idx & 127;
        int sel = orow >> 7, r = orow & 127;
        const float* w1 = (sel == 0) ? wq1 : (sel == 1) ? wk1 : (sel == 2) ? wv1 : ws1;
        const float* w2 = (sel == 0) ? wq2 : (sel == 1) ? wk2 : (sel == 2) ? wv2 : ws2;
        float v1 = w1[r * 128 + k], v2 = w2[r * 128 + k];
        if (sel == 0) { v1 *= QSCALE; v2 *= QSCALE; }
        g_Wh1[idx] = __float2half_rn(v1);
        g_Wh2[idx] = __float2half_rn(v2);
    }
    if (idx < 128 * 128) g_Whg[idx] = __float2half_rn(gw1[idx]);
    if (idx < 512) {
        int sel = idx >> 7, r = idx & 127;
        const float* b1 = (sel == 0) ? bq1 : (sel == 1) ? bk1 : (sel == 2) ? bv1 : bs1;
        const float* b2 = (sel == 0) ? bq2 : (sel == 1) ? bk2 : (sel == 2) ? bv2 : bs2;
        float v1 = b1[r], v2 = b2[r];
        if (sel == 0) { v1 *= QSCALE; v2 *= QSCALE; }
        g_B1[idx] = v1; g_B2[idx] = v2;
    }
    if (idx < 128) g_Bg[idx] = gb1[idx];
    if (idx < GGR * 128) g_pool[idx] = 0.f;
    if (idx < GGR) g_gs[idx] = 0.f;
}

// ---------------- fp16 mma GEMM: X loaded once, loop over N-tiles ----------------
#define KH 136
#define GEMM_SMEM_H (((128 + 64) * KH) * 2 + 512)   // + sgate[128] floats

template<bool GATEDOT, int NT, typename TIN>
__global__ __launch_bounds__(256, 2)
void gemm_h(const TIN* __restrict__ X, int n,
            const __half* __restrict__ Wh, const float* __restrict__ bias,
            const float* __restrict__ gw2d, const float* __restrict__ gb2,
            const int* __restrict__ batch) {
    extern __shared__ __half sh[];
    __half* sX = sh;               // [128][KH]
    __half* sW = sh + 128 * KH;    // [64][KH]
    float* sgate = (float*)(sh + (128 + 64) * KH);

    const int tid = threadIdx.x, wid = tid >> 5, lane = tid & 31;
    const int wm = wid & 3, wn = wid >> 2;
    const int row0 = blockIdx.x * 128;
    const int grp = lane >> 2, tg = lane & 3;

    if (GATEDOT && tid < 128) sgate[tid] = 0.f;

    // ---- X tile loaded ONCE ----
#pragma unroll
    for (int j = 0; j < 8; j++) {
        int idx = tid + 256 * j;
        int r = idx >> 4, c8 = idx & 15;
        int gr = row0 + r;
        uint4 pk = make_uint4(0u, 0u, 0u, 0u);
        if (gr < n) {
            if (sizeof(TIN) == 4) {
                const float* Xf = (const float*)X;
                float4 v0 = *(const float4*)(Xf + (size_t)gr * 128 + c8 * 8);
                float4 v1 = *(const float4*)(Xf + (size_t)gr * 128 + c8 * 8 + 4);
                __half2 h0 = __floats2half2_rn(v0.x, v0.y);
                __half2 h1 = __floats2half2_rn(v0.z, v0.w);
                __half2 h2 = __floats2half2_rn(v1.x, v1.y);
                __half2 h3 = __floats2half2_rn(v1.z, v1.w);
                pk.x = *(uint32_t*)&h0; pk.y = *(uint32_t*)&h1;
                pk.z = *(uint32_t*)&h2; pk.w = *(uint32_t*)&h3;
            } else {
                const __half* Xh = (const __half*)X;
                pk = *(const uint4*)(Xh + (size_t)gr * 128 + c8 * 8);
            }
        }
        *(uint4*)(sX + r * KH + c8 * 8) = pk;
    }

    float rp[2][2] = {{0.f, 0.f}, {0.f, 0.f}};

    for (int t = 0; t < NT; t++) {
        const int col0 = t * 64;
#pragma unroll
        for (int j = 0; j < 4; j++) {
            int idx = tid + 256 * j;
            int r = idx >> 4, c8 = idx & 15;
            *(uint4*)(sW + r * KH + c8 * 8) =
                *(const uint4*)(Wh + (size_t)(col0 + r) * 128 + c8 * 8);
        }
        __syncthreads();

        float acc[2][4][4];
#pragma unroll
        for (int mt = 0; mt < 2; mt++)
#pragma unroll
            for (int nt = 0; nt < 4; nt++)
#pragma unroll
                for (int q = 0; q < 4; q++) acc[mt][nt][q] = 0.f;

#pragma unroll
        for (int ks = 0; ks < 8; ks++) {
            const int c = ks * 16 + 2 * tg;
            uint32_t a[2][4];
#pragma unroll
            for (int mt = 0; mt < 2; mt++) {
                const int r = wm * 32 + mt * 16 + grp;
                a[mt][0] = *(const uint32_t*)(sX + r * KH + c);
                a[mt][1] = *(const uint32_t*)(sX + (r + 8) * KH + c);
                a[mt][2] = *(const uint32_t*)(sX + r * KH + c + 8);
                a[mt][3] = *(const uint32_t*)(sX + (r + 8) * KH + c + 8);
            }
            uint32_t b[4][2];
#pragma unroll
            for (int nt = 0; nt < 4; nt++) {
                const int nr = wn * 32 + nt * 8 + grp;
                b[nt][0] = *(const uint32_t*)(sW + nr * KH + c);
                b[nt][1] = *(const uint32_t*)(sW + nr * KH + c + 8);
            }
#pragma unroll
            for (int mt = 0; mt < 2; mt++)
#pragma unroll
                for (int nt = 0; nt < 4; nt++) mma16(acc[mt][nt], a[mt], b[nt]);
        }

        // ---- epilogue for this tile ----
#pragma unroll
        for (int mt = 0; mt < 2; mt++) {
            const int gr = row0 + wm * 32 + mt * 16 + grp;
#pragma unroll
            for (int nt = 0; nt < 4; nt++) {
                const int col = col0 + wn * 32 + nt * 8 + 2 * tg;
                const float b0 = bias[col], b1 = bias[col + 1];
                float2 o1 = make_float2(acc[mt][nt][0] + b0, acc[mt][nt][1] + b1);
                float2 o2 = make_float2(acc[mt][nt][2] + b0, acc[mt][nt][3] + b1);
                if (GATEDOT) {
                    o1.x = fmaxf(o1.x, 0.f); o1.y = fmaxf(o1.y, 0.f);
                    o2.x = fmaxf(o2.x, 0.f); o2.y = fmaxf(o2.y, 0.f);
                    const float w0 = gw2d[col], w1 = gw2d[col + 1];
                    rp[mt][0] += o1.x * w0 + o1.y * w1;
                    rp[mt][1] += o2.x * w0 + o2.y * w1;
                } else {
                    __half* dst0;
                    __half* dst1;
                    if (t < 2) {
                        dst0 = g_q16 + (size_t)gr * 128 + col;
                        dst1 = g_q16 + (size_t)(gr + 8) * 128 + col;
                    } else if (t < 6) {
                        dst0 = g_kv16 + (size_t)gr * 256 + (col - 128);
                        dst1 = g_kv16 + (size_t)(gr + 8) * 256 + (col - 128);
                    } else {
                        dst0 = g_sk16 + (size_t)gr * 128 + (col - 384);
                        dst1 = g_sk16 + (size_t)(gr + 8) * 128 + (col - 384);
                    }
                    if (gr < n)     *(__half2*)dst0 = __floats2half2_rn(o1.x, o1.y);
                    if (gr + 8 < n) *(__half2*)dst1 = __floats2half2_rn(o2.x, o2.y);
                }
            }
        }
        __syncthreads();   // protect sW before next tile's load
    }

    if (GATEDOT) {
        // warp-local reduce over tg, accumulate into smem, then exp + graph sums
#pragma unroll
        for (int mt = 0; mt < 2; mt++)
#pragma unroll
            for (int h = 0; h < 2; h++) {
                float v = rp[mt][h];
                v += __shfl_xor_sync(0xffffffffu, v, 1);
                v += __shfl_xor_sync(0xffffffffu, v, 2);
                if (tg == 0)
                    atomicAdd(&sgate[wm * 32 + mt * 16 + grp + h * 8], v);
            }
        __syncthreads();
        if (tid < 128) {
            const int row = row0 + tid;
            if (row < n) {
                float ev = __expf(sgate[tid] + gb2[0]);
                g_gate[row] = ev;
                atomicAdd(&g_gs[batch[row]], ev);
            }
        }
    }
}

// ================= CSR build =================
__global__ void hist_zero(int n) {
    int i = blockIdx.x * blockDim.x + threadIdx.x;
    if (i < n) g_cur[i] = 0;
}
__global__ void hist(const int* __restrict__ dst, int E) {
    int e = blockIdx.x * blockDim.x + threadIdx.x;
    if (e < E) atomicAdd(&g_cur[dst[e]], 1);
}
__global__ void scan_blocks(int n) {
    __shared__ int sm[256];
    int t = threadIdx.x;
    int i = blockIdx.x * 256 + t;
    int v = (i < n) ? g_cur[i] : 0;
    sm[t] = v;
    __syncthreads();
#pragma unroll
    for (int o = 1; o < 256; o <<= 1) {
        int x = (t >= o) ? sm[t - o] : 0;
        __syncthreads();
        sm[t] += x;
        __syncthreads();
    }
    if (i < n) g_off[i] = sm[t] - v;
    if (t == 255) g_bsums[blockIdx.x] = sm[255];
}
__global__ void scan_tops(int nblk) {
    __shared__ int sm[512];
    int t = threadIdx.x;
    int v = (t < nblk) ? g_bsums[t] : 0;
    sm[t] = v;
    __syncthreads();
#pragma unroll
    for (int o = 1; o < 512; o <<= 1) {
        int x = (t >= o) ? sm[t - o] : 0;
        __syncthreads();
        sm[t] += x;
        __syncthreads();
    }
    if (t < nblk) g_bsums[t] = sm[t] - v;
}
__global__ void scan_add(int n, int E) {
    int i = blockIdx.x * 256 + threadIdx.x;
    if (i < n) {
        int o = g_off[i] + g_bsums[blockIdx.x];
        g_off[i] = o;
        g_cur[i] = o;
    }
    if (i == 0) g_off[n] = E;
}
__global__ void fill_csr(const int* __restrict__ src, const int* __restrict__ dst, int E) {
    int e = blockIdx.x * blockDim.x + threadIdx.x;
    if (e >= E) return;
    int p = atomicAdd(&g_cur[dst[e]], 1);
    g_csrc[p] = src[e];
}

// ================= fused per-node attention: 1 uint4 gather per edge =================
// lanes 0-15 own q (8 feats/lane) and compute the dot; lanes 16-31 own skip and
// accumulate v. One warp-wide 16B/lane load covers the whole 512B kv record.
__global__ __launch_bounds__(256, 5)
void node_attn(int n) {
    int node = (blockIdx.x * blockDim.x + threadIdx.x) >> 5;
    int lane = threadIdx.x & 31;
    if (node >= n) return;
    const bool hi = lane >= 16;
    const int sub = lane & 15;            // feature chunk within half

    // lanes<16: q chunk; lanes>=16: skip chunk
    const __half* qsp = hi ? (g_sk16 + (size_t)node * 128 + sub * 8)
                           : (g_q16 + (size_t)node * 128 + sub * 8);
    uint4 qsr = *(const uint4*)qsp;
    float qv[8];
    unpack8(qsr, qv);

    int beg = g_off[node], end = g_off[node + 1];
    float acc[8];
#pragma unroll
    for (int i = 0; i < 8; i++) acc[i] = 0.f;
    float sum = 0.f;

    int j = beg;
    for (; j + 4 <= end; j += 4) {
        uint4 kv[4];
#pragma unroll
        for (int u = 0; u < 4; u++)
            kv[u] = *(const uint4*)(g_kv16 + (size_t)g_csrc[j + u] * 256 + lane * 8);

        float d[4];
#pragma unroll
        for (int u = 0; u < 4; u++) {
            float f[8];
            unpack8(kv[u], f);
            d[u] = qv[0] * f[0] + qv[1] * f[1] + qv[2] * f[2] + qv[3] * f[3]
                 + qv[4] * f[4] + qv[5] * f[5] + qv[6] * f[6] + qv[7] * f[7];
        }
#pragma unroll
        for (int o = 8; o; o >>= 1) {
#pragma unroll
            for (int u = 0; u < 4; u++) d[u] += __shfl_xor_sync(0xffffffffu, d[u], o);
        }
        float e[4];
#pragma unroll
        for (int u = 0; u < 4; u++) {
            e[u] = __expf(__shfl_sync(0xffffffffu, d[u], 0));
            sum += e[u];
        }
#pragma unroll
        for (int u = 0; u < 4; u++) {
            float f[8];
            unpack8(kv[u], f);
#pragma unroll
            for (int i = 0; i < 8; i++) acc[i] += e[u] * f[i];
        }
    }
    for (; j < end; j++) {
        uint4 kv = *(const uint4*)(g_kv16 + (size_t)g_csrc[j] * 256 + lane * 8);
        float f[8];
        unpack8(kv, f);
        float d0 = qv[0] * f[0] + qv[1] * f[1] + qv[2] * f[2] + qv[3] * f[3]
                 + qv[4] * f[4] + qv[5] * f[5] + qv[6] * f[6] + qv[7] * f[7];
#pragma unroll
        for (int o = 8; o; o >>= 1) d0 += __shfl_xor_sync(0xffffffffu, d0, o);
        float e0 = __expf(__shfl_sync(0xffffffffu, d0, 0));
        sum += e0;
#pragma unroll
        for (int i = 0; i < 8; i++) acc[i] += e0 * f[i];
    }

    // lanes 16-31 hold v-accumulators; combine with skip (in qv) and write
    if (hi) {
        float inv = (end > beg) ? (1.f / sum) : 0.f;
        uint4 outp;
        __half2* op = (__half2*)&outp;
#pragma unroll
        for (int i = 0; i < 4; i++) {
            float o0 = fmaxf(acc[2 * i] * inv + qv[2 * i], 0.f);
            float o1 = fmaxf(acc[2 * i + 1] * inv + qv[2 * i + 1], 0.f);
            op[i] = __floats2half2_rn(o0, o1);
        }
        *(uint4*)(g_h16 + (size_t)node * 128 + sub * 8) = outp;
    }
}

// ---------------- graph-level ----------------
#define POOL_CHUNK 512
__global__ void pool_kernel(const int* __restrict__ batch, int n) {
    int d = threadIdx.x;
    int n0 = blockIdx.x * POOL_CHUNK;
    int n1 = min(n0 + POOL_CHUNK, n);
    if (n0 >= n) return;
    int curb = batch[n0];
    float acc = 0.f;
    for (int node = n0; node < n1; node++) {
        int b = batch[node];
        if (b != curb) {
            atomicAdd(&g_pool[curb * 128 + d], acc);
            acc = 0.f; curb = b;
        }
        float wgt = g_gate[node] / g_gs[b];
        acc += wgt * __half2float(g_h16[(size_t)node * 128 + d]);
    }
    atomicAdd(&g_pool[curb * 128 + d], acc);
}

__global__ void classifier(const float* __restrict__ cw, const float* __restrict__ cb,
                           float* __restrict__ out) {
    int i = threadIdx.x;
    if (i >= GGR * 10) return;
    int g = i / 10, c = i % 10;
    float a = cb[c];
#pragma unroll 16
    for (int k = 0; k < 128; k++) a += g_pool[g * 128 + k] * cw[c * 128 + k];
    out[i] = a;
}

// ---------------- host orchestration ----------------
extern "C" void kernel_launch(void* const* d_in, const int* in_sizes, int n_in,
                              void* d_out, int out_size) {
    const float* x   = (const float*)d_in[0];
    const int* eidx  = (const int*)d_in[1];
    const int* batch = (const int*)d_in[2];
    const float *wq1 = (const float*)d_in[3],  *bq1 = (const float*)d_in[4];
    const float *wk1 = (const float*)d_in[5],  *bk1 = (const float*)d_in[6];
    const float *wv1 = (const float*)d_in[7],  *bv1 = (const float*)d_in[8];
    const float *ws1 = (const float*)d_in[9],  *bs1 = (const float*)d_in[10];
    const float *wq2 = (const float*)d_in[11], *bq2 = (const float*)d_in[12];
    const float *wk2 = (const float*)d_in[13], *bk2 = (const float*)d_in[14];
    const float *wv2 = (const float*)d_in[15], *bv2 = (const float*)d_in[16];
    const float *ws2 = (const float*)d_in[17], *bs2 = (const float*)d_in[18];
    const float *gw1 = (const float*)d_in[19], *gb1 = (const float*)d_in[20];
    const float *gw2 = (const float*)d_in[21], *gb2 = (const float*)d_in[22];
    const float *cw  = (const float*)d_in[23], *cb  = (const float*)d_in[24];
    float* out = (float*)d_out;

    const int n = in_sizes[0] / 128;
    const int E = in_sizes[1] / 2;
    const int* src = eidx;
    const int* dst = eidx + E;

    static __half *p_h16 = nullptr, *p_Wh1 = nullptr, *p_Wh2 = nullptr, *p_Whg = nullptr;
    static float  *p_B1 = nullptr,  *p_B2 = nullptr,  *p_Bg = nullptr;
    if (!p_h16) {
        cudaGetSymbolAddress((void**)&p_h16,  g_h16);
        cudaGetSymbolAddress((void**)&p_Wh1,  g_Wh1);
        cudaGetSymbolAddress((void**)&p_Wh2,  g_Wh2);
        cudaGetSymbolAddress((void**)&p_Whg,  g_Whg);
        cudaGetSymbolAddress((void**)&p_B1,   g_B1);
        cudaGetSymbolAddress((void**)&p_B2,   g_B2);
        cudaGetSymbolAddress((void**)&p_Bg,   g_Bg);
        cudaFuncSetAttribute((const void*)gemm_h<false, 8, float>,
                             cudaFuncAttributeMaxDynamicSharedMemorySize, GEMM_SMEM_H);
        cudaFuncSetAttribute((const void*)gemm_h<false, 8, __half>,
                             cudaFuncAttributeMaxDynamicSharedMemorySize, GEMM_SMEM_H);
        cudaFuncSetAttribute((const void*)gemm_h<true, 2, __half>,
                             cudaFuncAttributeMaxDynamicSharedMemorySize, GEMM_SMEM_H);
    }

    const int nwb  = (n + 255) / 256;
    const int etb  = (E + 255) / 256;
    const int nblk = (n + 255) / 256;
    const int nab  = (n * 32 + 255) / 256;      // 1 warp/node
    const int mtiles = (n + 127) / 128;

    // ---- combined packs + graph init ----
    pack_all<<<(512 * 128 + 255) / 256, 256>>>(wq1, bq1, wk1, bk1, wv1, bv1, ws1, bs1,
                                               wq2, bq2, wk2, bk2, wv2, bv2, ws2, bs2,
                                               gw1, gb1);

    // ---- CSR build ----
    hist_zero<<<nwb, 256>>>(n);
    hist<<<etb, 256>>>(dst, E);
    scan_blocks<<<nblk, 256>>>(n);
    scan_tops<<<1, 512>>>(nblk);
    scan_add<<<nblk, 256>>>(n, E);
    fill_csr<<<etb, 256>>>(src, dst, E);

    // ---- Layer 1 (fp32 input) ----
    gemm_h<false, 8, float><<<mtiles, 256, GEMM_SMEM_H>>>(x, n, p_Wh1, p_B1,
                                                          nullptr, nullptr, nullptr);
    node_attn<<<nab, 256>>>(n);

    // ---- Layer 2 (fp16 input) ----
    gemm_h<false, 8, __half><<<mtiles, 256, GEMM_SMEM_H>>>(p_h16, n, p_Wh2, p_B2,
                                                           nullptr, nullptr, nullptr);
    node_attn<<<nab, 256>>>(n);

    // ---- Global attention (gate dot + exp + graph sums fused into GEMM) ----
    gemm_h<true, 2, __half><<<mtiles, 256, GEMM_SMEM_H>>>(p_h16, n, p_Whg, p_Bg,
                                                          gw2, gb2, batch);
    pool_kernel<<<(n + POOL_CHUNK - 1) / POOL_CHUNK, 128>>>(batch, n);

    // ---- Classifier ----
    classifier<<<1, 1024>>>(cw, cb, out);
}

// round 14
// speedup vs baseline: 1.4101x; 1.4101x over previous
#include <cuda_runtime.h>
#include <cuda_fp16.h>
#include <cstdint>

// Problem constants
#define NN 100000
#define EE 1600000
#define GGR 64

// ---------------- static device scratch (all intermediates fp16) ----------------
__device__ __half   g_q16 [(size_t)NN * 128];  // q, pre-scaled by 1/sqrt(128)
__device__ __half   g_kv16[(size_t)NN * 256];  // k[0:128) v[128:256)
__device__ __half   g_sk16[(size_t)NN * 128];  // skip connection
__device__ __half   g_h16 [(size_t)NN * 128];  // layer output
__device__ float    g_gate[NN];                // exp(gate logit)
__device__ float    g_pool[GGR * 128];
__device__ float    g_gs[GGR];
__device__ __half   g_Wh1[512 * 128];
__device__ __half   g_Wh2[512 * 128];
__device__ __half   g_Whg[128 * 128];
__device__ float    g_B1[512];
__device__ float    g_B2[512];
__device__ float    g_Bg[128];
// CSR (dst-sorted adjacency)
__device__ int      g_off[NN + 1];
__device__ int      g_cur[NN];
__device__ int      g_csrc[EE];
__device__ int      g_bsums[512];

#define QSCALE 0.08838834764831845f   // 1/sqrt(128)

// ---------------- fp16 mma ----------------
__device__ __forceinline__ void mma16(float* d, const uint32_t* a, const uint32_t* b) {
    asm volatile("mma.sync.aligned.m16n8k16.row.col.f32.f16.f16.f32 "
        "{%0,%1,%2,%3}, {%4,%5,%6,%7}, {%8,%9}, {%0,%1,%2,%3};"
        : "+f"(d[0]), "+f"(d[1]), "+f"(d[2]), "+f"(d[3])
        : "r"(a[0]), "r"(a[1]), "r"(a[2]), "r"(a[3]), "r"(b[0]), "r"(b[1]));
}

// ---------------- combined packing + graph init ----------------
__global__ void pack_all(const float* __restrict__ wq1, const float* __restrict__ bq1,
                         const float* __restrict__ wk1, const float* __restrict__ bk1,
                         const float* __restrict__ wv1, const float* __restrict__ bv1,
                         const float* __restrict__ ws1, const float* __restrict__ bs1,
                         const float* __restrict__ wq2, const float* __restrict__ bq2,
                         const float* __restrict__ wk2, const float* __restrict__ bk2,
                         const float* __restrict__ wv2, const float* __restrict__ bv2,
                         const float* __restrict__ ws2, const float* __restrict__ bs2,
                         const float* __restrict__ gw1, const float* __restrict__ gb1) {
    int idx = blockIdx.x * blockDim.x + threadIdx.x;
    if (idx < 512 * 128) {
        int orow = idx >> 7, k = idx & 127;
        int sel = orow >> 7, r = orow & 127;
        const float* w1 = (sel == 0) ? wq1 : (sel == 1) ? wk1 : (sel == 2) ? wv1 : ws1;
        const float* w2 = (sel == 0) ? wq2 : (sel == 1) ? wk2 : (sel == 2) ? wv2 : ws2;
        float v1 = w1[r * 128 + k], v2 = w2[r * 128 + k];
        if (sel == 0) { v1 *= QSCALE; v2 *= QSCALE; }
        g_Wh1[idx] = __float2half_rn(v1);
        g_Wh2[idx] = __float2half_rn(v2);
    }
    if (idx < 128 * 128) g_Whg[idx] = __float2half_rn(gw1[idx]);
    if (idx < 512) {
        int sel = idx >> 7, r = idx & 127;
        const float* b1 = (sel == 0) ? bq1 : (sel == 1) ? bk1 : (sel == 2) ? bv1 : bs1;
        const float* b2 = (sel == 0) ? bq2 : (sel == 1) ? bk2 : (sel == 2) ? bv2 : bs2;
        float v1 = b1[r], v2 = b2[r];
        if (sel == 0) { v1 *= QSCALE; v2 *= QSCALE; }
        g_B1[idx] = v1; g_B2[idx] = v2;
    }
    if (idx < 128) g_Bg[idx] = gb1[idx];
    if (idx < GGR * 128) g_pool[idx] = 0.f;
    if (idx < GGR) g_gs[idx] = 0.f;
}

// ---------------- fp16 mma GEMM: X loaded once, loop over N-tiles ----------------
#define KH 136
#define GEMM_SMEM_H (((128 + 64) * KH) * 2 + 512)   // + sgate[128] floats

template<bool GATEDOT, int NT, typename TIN>
__global__ __launch_bounds__(256, 2)
void gemm_h(const TIN* __restrict__ X, int n,
            const __half* __restrict__ Wh, const float* __restrict__ bias,
            const float* __restrict__ gw2d, const float* __restrict__ gb2,
            const int* __restrict__ batch) {
    extern __shared__ __half sh[];
    __half* sX = sh;               // [128][KH]
    __half* sW = sh + 128 * KH;    // [64][KH]
    float* sgate = (float*)(sh + (128 + 64) * KH);

    const int tid = threadIdx.x, wid = tid >> 5, lane = tid & 31;
    const int wm = wid & 3, wn = wid >> 2;
    const int row0 = blockIdx.x * 128;
    const int grp = lane >> 2, tg = lane & 3;

    if (GATEDOT && tid < 128) sgate[tid] = 0.f;

    // ---- X tile loaded ONCE ----
#pragma unroll
    for (int j = 0; j < 8; j++) {
        int idx = tid + 256 * j;
        int r = idx >> 4, c8 = idx & 15;
        int gr = row0 + r;
        uint4 pk = make_uint4(0u, 0u, 0u, 0u);
        if (gr < n) {
            if (sizeof(TIN) == 4) {
                const float* Xf = (const float*)X;
                float4 v0 = *(const float4*)(Xf + (size_t)gr * 128 + c8 * 8);
                float4 v1 = *(const float4*)(Xf + (size_t)gr * 128 + c8 * 8 + 4);
                __half2 h0 = __floats2half2_rn(v0.x, v0.y);
                __half2 h1 = __floats2half2_rn(v0.z, v0.w);
                __half2 h2 = __floats2half2_rn(v1.x, v1.y);
                __half2 h3 = __floats2half2_rn(v1.z, v1.w);
                pk.x = *(uint32_t*)&h0; pk.y = *(uint32_t*)&h1;
                pk.z = *(uint32_t*)&h2; pk.w = *(uint32_t*)&h3;
            } else {
                const __half* Xh = (const __half*)X;
                pk = *(const uint4*)(Xh + (size_t)gr * 128 + c8 * 8);
            }
        }
        *(uint4*)(sX + r * KH + c8 * 8) = pk;
    }

    float rp[2][2] = {{0.f, 0.f}, {0.f, 0.f}};

    for (int t = 0; t < NT; t++) {
        const int col0 = t * 64;
#pragma unroll
        for (int j = 0; j < 4; j++) {
            int idx = tid + 256 * j;
            int r = idx >> 4, c8 = idx & 15;
            *(uint4*)(sW + r * KH + c8 * 8) =
                *(const uint4*)(Wh + (size_t)(col0 + r) * 128 + c8 * 8);
        }
        __syncthreads();

        float acc[2][4][4];
#pragma unroll
        for (int mt = 0; mt < 2; mt++)
#pragma unroll
            for (int nt = 0; nt < 4; nt++)
#pragma unroll
                for (int q = 0; q < 4; q++) acc[mt][nt][q] = 0.f;

#pragma unroll
        for (int ks = 0; ks < 8; ks++) {
            const int c = ks * 16 + 2 * tg;
            uint32_t a[2][4];
#pragma unroll
            for (int mt = 0; mt < 2; mt++) {
                const int r = wm * 32 + mt * 16 + grp;
                a[mt][0] = *(const uint32_t*)(sX + r * KH + c);
                a[mt][1] = *(const uint32_t*)(sX + (r + 8) * KH + c);
                a[mt][2] = *(const uint32_t*)(sX + r * KH + c + 8);
                a[mt][3] = *(const uint32_t*)(sX + (r + 8) * KH + c + 8);
            }
            uint32_t b[4][2];
#pragma unroll
            for (int nt = 0; nt < 4; nt++) {
                const int nr = wn * 32 + nt * 8 + grp;
                b[nt][0] = *(const uint32_t*)(sW + nr * KH + c);
                b[nt][1] = *(const uint32_t*)(sW + nr * KH + c + 8);
            }
#pragma unroll
            for (int mt = 0; mt < 2; mt++)
#pragma unroll
                for (int nt = 0; nt < 4; nt++) mma16(acc[mt][nt], a[mt], b[nt]);
        }

        // ---- epilogue for this tile ----
#pragma unroll
        for (int mt = 0; mt < 2; mt++) {
            const int gr = row0 + wm * 32 + mt * 16 + grp;
#pragma unroll
            for (int nt = 0; nt < 4; nt++) {
                const int col = col0 + wn * 32 + nt * 8 + 2 * tg;
                const float b0 = bias[col], b1 = bias[col + 1];
                float2 o1 = make_float2(acc[mt][nt][0] + b0, acc[mt][nt][1] + b1);
                float2 o2 = make_float2(acc[mt][nt][2] + b0, acc[mt][nt][3] + b1);
                if (GATEDOT) {
                    o1.x = fmaxf(o1.x, 0.f); o1.y = fmaxf(o1.y, 0.f);
                    o2.x = fmaxf(o2.x, 0.f); o2.y = fmaxf(o2.y, 0.f);
                    const float w0 = gw2d[col], w1 = gw2d[col + 1];
                    rp[mt][0] += o1.x * w0 + o1.y * w1;
                    rp[mt][1] += o2.x * w0 + o2.y * w1;
                } else {
                    __half* dst0;
                    __half* dst1;
                    if (t < 2) {
                        dst0 = g_q16 + (size_t)gr * 128 + col;
                        dst1 = g_q16 + (size_t)(gr + 8) * 128 + col;
                    } else if (t < 6) {
                        dst0 = g_kv16 + (size_t)gr * 256 + (col - 128);
                        dst1 = g_kv16 + (size_t)(gr + 8) * 256 + (col - 128);
                    } else {
                        dst0 = g_sk16 + (size_t)gr * 128 + (col - 384);
                        dst1 = g_sk16 + (size_t)(gr + 8) * 128 + (col - 384);
                    }
                    if (gr < n)     *(__half2*)dst0 = __floats2half2_rn(o1.x, o1.y);
                    if (gr + 8 < n) *(__half2*)dst1 = __floats2half2_rn(o2.x, o2.y);
                }
            }
        }
        __syncthreads();   // protect sW before next tile's load
    }

    if (GATEDOT) {
#pragma unroll
        for (int mt = 0; mt < 2; mt++)
#pragma unroll
            for (int h = 0; h < 2; h++) {
                float v = rp[mt][h];
                v += __shfl_xor_sync(0xffffffffu, v, 1);
                v += __shfl_xor_sync(0xffffffffu, v, 2);
                if (tg == 0)
                    atomicAdd(&sgate[wm * 32 + mt * 16 + grp + h * 8], v);
            }
        __syncthreads();
        if (tid < 128) {
            const int row = row0 + tid;
            if (row < n) {
                float ev = __expf(sgate[tid] + gb2[0]);
                g_gate[row] = ev;
                atomicAdd(&g_gs[batch[row]], ev);
            }
        }
    }
}

// ================= CSR build =================
__global__ void hist_zero(int n) {
    int i = blockIdx.x * blockDim.x + threadIdx.x;
    if (i < n) g_cur[i] = 0;
}
__global__ void hist(const int* __restrict__ dst, int E) {
    int e = blockIdx.x * blockDim.x + threadIdx.x;
    if (e < E) atomicAdd(&g_cur[dst[e]], 1);
}
__global__ void scan_blocks(int n) {
    __shared__ int sm[256];
    int t = threadIdx.x;
    int i = blockIdx.x * 256 + t;
    int v = (i < n) ? g_cur[i] : 0;
    sm[t] = v;
    __syncthreads();
#pragma unroll
    for (int o = 1; o < 256; o <<= 1) {
        int x = (t >= o) ? sm[t - o] : 0;
        __syncthreads();
        sm[t] += x;
        __syncthreads();
    }
    if (i < n) g_off[i] = sm[t] - v;
    if (t == 255) g_bsums[blockIdx.x] = sm[255];
}
__global__ void scan_tops(int nblk) {
    __shared__ int sm[512];
    int t = threadIdx.x;
    int v = (t < nblk) ? g_bsums[t] : 0;
    sm[t] = v;
    __syncthreads();
#pragma unroll
    for (int o = 1; o < 512; o <<= 1) {
        int x = (t >= o) ? sm[t - o] : 0;
        __syncthreads();
        sm[t] += x;
        __syncthreads();
    }
    if (t < nblk) g_bsums[t] = sm[t] - v;
}
__global__ void scan_add(int n, int E) {
    int i = blockIdx.x * 256 + threadIdx.x;
    if (i < n) {
        int o = g_off[i] + g_bsums[blockIdx.x];
        g_off[i] = o;
        g_cur[i] = o;
    }
    if (i == 0) g_off[n] = E;
}
__global__ void fill_csr(const int* __restrict__ src, const int* __restrict__ dst, int E) {
    int e = blockIdx.x * blockDim.x + threadIdx.x;
    if (e >= E) return;
    int p = atomicAdd(&g_cur[dst[e]], 1);
    g_csrc[p] = src[e];
}

// ================= fused per-node attention (round-12 proven shape) =================
__global__ __launch_bounds__(256, 6)
void node_attn(int n) {
    int node = (blockIdx.x * blockDim.x + threadIdx.x) >> 5;
    int lane = threadIdx.x & 31;
    if (node >= n) return;

    uint2 qp = *(const uint2*)(g_q16 + (size_t)node * 128 + lane * 4);
    float2 q01 = __half22float2(*(const __half2*)&qp.x);
    float2 q23 = __half22float2(*(const __half2*)&qp.y);
    float4 q = make_float4(q01.x, q01.y, q23.x, q23.y);

    int beg = g_off[node], end = g_off[node + 1];
    float4 acc = make_float4(0.f, 0.f, 0.f, 0.f);
    float sum = 0.f;

    int j = beg;
    for (; j + 4 <= end; j += 4) {
        const __half* r[4];
#pragma unroll
        for (int u = 0; u < 4; u++) r[u] = g_kv16 + (size_t)g_csrc[j + u] * 256;
        uint2 kk[4], vv[4];
#pragma unroll
        for (int u = 0; u < 4; u++) kk[u] = *(const uint2*)(r[u] + lane * 4);
#pragma unroll
        for (int u = 0; u < 4; u++) vv[u] = *(const uint2*)(r[u] + 128 + lane * 4);

        float d[4];
#pragma unroll
        for (int u = 0; u < 4; u++) {
            float2 a = __half22float2(*(const __half2*)&kk[u].x);
            float2 b = __half22float2(*(const __half2*)&kk[u].y);
            d[u] = q.x * a.x + q.y * a.y + q.z * b.x + q.w * b.y;
        }
#pragma unroll
        for (int o = 16; o; o >>= 1) {
#pragma unroll
            for (int u = 0; u < 4; u++) d[u] += __shfl_xor_sync(0xffffffffu, d[u], o);
        }
#pragma unroll
        for (int u = 0; u < 4; u++) {
            float e = __expf(d[u]);
            float2 va = __half22float2(*(const __half2*)&vv[u].x);
            float2 vb = __half22float2(*(const __half2*)&vv[u].y);
            acc.x += e * va.x; acc.y += e * va.y;
            acc.z += e * vb.x; acc.w += e * vb.y;
            sum += e;
        }
    }
    for (; j < end; j++) {
        const __half* r0 = g_kv16 + (size_t)g_csrc[j] * 256;
        uint2 kk = *(const uint2*)(r0 + lane * 4);
        uint2 vv = *(const uint2*)(r0 + 128 + lane * 4);
        float2 a = __half22float2(*(const __half2*)&kk.x);
        float2 b = __half22float2(*(const __half2*)&kk.y);
        float d0 = q.x * a.x + q.y * a.y + q.z * b.x + q.w * b.y;
#pragma unroll
        for (int o = 16; o; o >>= 1) d0 += __shfl_xor_sync(0xffffffffu, d0, o);
        float e0 = __expf(d0);
        float2 va = __half22float2(*(const __half2*)&vv.x);
        float2 vb = __half22float2(*(const __half2*)&vv.y);
        acc.x += e0 * va.x; acc.y += e0 * va.y;
        acc.z += e0 * vb.x; acc.w += e0 * vb.y;
        sum += e0;
    }

    float inv = (end > beg) ? (1.f / sum) : 0.f;
    uint2 sp = *(const uint2*)(g_sk16 + (size_t)node * 128 + lane * 4);
    float2 s01 = __half22float2(*(const __half2*)&sp.x);
    float2 s23 = __half22float2(*(const __half2*)&sp.y);
    float ox = fmaxf(acc.x * inv + s01.x, 0.f);
    float oy = fmaxf(acc.y * inv + s01.y, 0.f);
    float oz = fmaxf(acc.z * inv + s23.x, 0.f);
    float ow = fmaxf(acc.w * inv + s23.y, 0.f);
    uint2 outp;
    *(__half2*)&outp.x = __floats2half2_rn(ox, oy);
    *(__half2*)&outp.y = __floats2half2_rn(oz, ow);
    *(uint2*)(g_h16 + (size_t)node * 128 + lane * 4) = outp;
}

// ---------------- graph-level ----------------
#define POOL_CHUNK 512
__global__ void pool_kernel(const int* __restrict__ batch, int n) {
    int d = threadIdx.x;
    int n0 = blockIdx.x * POOL_CHUNK;
    int n1 = min(n0 + POOL_CHUNK, n);
    if (n0 >= n) return;
    int curb = batch[n0];
    float acc = 0.f;
    for (int node = n0; node < n1; node++) {
        int b = batch[node];
        if (b != curb) {
            atomicAdd(&g_pool[curb * 128 + d], acc);
            acc = 0.f; curb = b;
        }
        float wgt = g_gate[node] / g_gs[b];
        acc += wgt * __half2float(g_h16[(size_t)node * 128 + d]);
    }
    atomicAdd(&g_pool[curb * 128 + d], acc);
}

__global__ void classifier(const float* __restrict__ cw, const float* __restrict__ cb,
                           float* __restrict__ out) {
    int i = threadIdx.x;
    if (i >= GGR * 10) return;
    int g = i / 10, c = i % 10;
    float a = cb[c];
#pragma unroll 16
    for (int k = 0; k < 128; k++) a += g_pool[g * 128 + k] * cw[c * 128 + k];
    out[i] = a;
}

// ---------------- host orchestration ----------------
extern "C" void kernel_launch(void* const* d_in, const int* in_sizes, int n_in,
                              void* d_out, int out_size) {
    const float* x   = (const float*)d_in[0];
    const int* eidx  = (const int*)d_in[1];
    const int* batch = (const int*)d_in[2];
    const float *wq1 = (const float*)d_in[3],  *bq1 = (const float*)d_in[4];
    const float *wk1 = (const float*)d_in[5],  *bk1 = (const float*)d_in[6];
    const float *wv1 = (const float*)d_in[7],  *bv1 = (const float*)d_in[8];
    const float *ws1 = (const float*)d_in[9],  *bs1 = (const float*)d_in[10];
    const float *wq2 = (const float*)d_in[11], *bq2 = (const float*)d_in[12];
    const float *wk2 = (const float*)d_in[13], *bk2 = (const float*)d_in[14];
    const float *wv2 = (const float*)d_in[15], *bv2 = (const float*)d_in[16];
    const float *ws2 = (const float*)d_in[17], *bs2 = (const float*)d_in[18];
    const float *gw1 = (const float*)d_in[19], *gb1 = (const float*)d_in[20];
    const float *gw2 = (const float*)d_in[21], *gb2 = (const float*)d_in[22];
    const float *cw  = (const float*)d_in[23], *cb  = (const float*)d_in[24];
    float* out = (float*)d_out;

    const int n = in_sizes[0] / 128;
    const int E = in_sizes[1] / 2;
    const int* src = eidx;
    const int* dst = eidx + E;

    static __half *p_h16 = nullptr, *p_Wh1 = nullptr, *p_Wh2 = nullptr, *p_Whg = nullptr;
    static float  *p_B1 = nullptr,  *p_B2 = nullptr,  *p_Bg = nullptr;
    if (!p_h16) {
        cudaGetSymbolAddress((void**)&p_h16,  g_h16);
        cudaGetSymbolAddress((void**)&p_Wh1,  g_Wh1);
        cudaGetSymbolAddress((void**)&p_Wh2,  g_Wh2);
        cudaGetSymbolAddress((void**)&p_Whg,  g_Whg);
        cudaGetSymbolAddress((void**)&p_B1,   g_B1);
        cudaGetSymbolAddress((void**)&p_B2,   g_B2);
        cudaGetSymbolAddress((void**)&p_Bg,   g_Bg);
        cudaFuncSetAttribute((const void*)gemm_h<false, 8, float>,
                             cudaFuncAttributeMaxDynamicSharedMemorySize, GEMM_SMEM_H);
        cudaFuncSetAttribute((const void*)gemm_h<false, 8, __half>,
                             cudaFuncAttributeMaxDynamicSharedMemorySize, GEMM_SMEM_H);
        cudaFuncSetAttribute((const void*)gemm_h<true, 2, __half>,
                             cudaFuncAttributeMaxDynamicSharedMemorySize, GEMM_SMEM_H);
    }

    const int nwb  = (n + 255) / 256;
    const int etb  = (E + 255) / 256;
    const int nblk = (n + 255) / 256;
    const int nab  = (n * 32 + 255) / 256;      // 1 warp/node
    const int mtiles = (n + 127) / 128;

    // ---- combined packs + graph init ----
    pack_all<<<(512 * 128 + 255) / 256, 256>>>(wq1, bq1, wk1, bk1, wv1, bv1, ws1, bs1,
                                               wq2, bq2, wk2, bk2, wv2, bv2, ws2, bs2,
                                               gw1, gb1);

    // ---- CSR build ----
    hist_zero<<<nwb, 256>>>(n);
    hist<<<etb, 256>>>(dst, E);
    scan_blocks<<<nblk, 256>>>(n);
    scan_tops<<<1, 512>>>(nblk);
    scan_add<<<nblk, 256>>>(n, E);
    fill_csr<<<etb, 256>>>(src, dst, E);

    // ---- Layer 1 (fp32 input) ----
    gemm_h<false, 8, float><<<mtiles, 256, GEMM_SMEM_H>>>(x, n, p_Wh1, p_B1,
                                                          nullptr, nullptr, nullptr);
    node_attn<<<nab, 256>>>(n);

    // ---- Layer 2 (fp16 input) ----
    gemm_h<false, 8, __half><<<mtiles, 256, GEMM_SMEM_H>>>(p_h16, n, p_Wh2, p_B2,
                                                           nullptr, nullptr, nullptr);
    node_attn<<<nab, 256>>>(n);

    // ---- Global attention (gate dot + exp + graph sums fused into GEMM) ----
    gemm_h<true, 2, __half><<<mtiles, 256, GEMM_SMEM_H>>>(p_h16, n, p_Whg, p_Bg,
                                                          gw2, gb2, batch);
    pool_kernel<<<(n + POOL_CHUNK - 1) / POOL_CHUNK, 128>>>(batch, n);

    // ---- Classifier ----
    classifier<<<1, 1024>>>(cw, cb, out);
}

// round 16
// speedup vs baseline: 1.4106x; 1.0004x over previous
#include <cuda_runtime.h>
#include <cuda_fp16.h>
#include <cstdint>

// Problem constants
#define NN 100000
#define EE 1600000
#define GGR 64

// ---------------- static device scratch (all intermediates fp16) ----------------
__device__ __align__(16) __half g_q16 [(size_t)NN * 128];  // q, pre-scaled by 1/sqrt(128)
__device__ __align__(16) __half g_kv16[(size_t)NN * 256];  // k[0:128) v[128:256)
__device__ __align__(16) __half g_sk16[(size_t)NN * 128];  // skip connection
__device__ __align__(16) __half g_h16 [(size_t)NN * 128];  // layer output
__device__ float    g_gate[NN];                // exp(gate logit)
__device__ float    g_pool[GGR * 128];
__device__ float    g_gs[GGR];
__device__ __align__(16) __half g_Wh1[512 * 128];
__device__ __align__(16) __half g_Wh2[512 * 128];
__device__ __align__(16) __half g_Whg[128 * 128];
__device__ float    g_B1[512];
__device__ float    g_B2[512];
__device__ float    g_Bg[128];
// CSR (dst-sorted adjacency)
__device__ int      g_off[NN + 1];
__device__ int      g_cur[NN];
__device__ int      g_csrc[EE];
__device__ int      g_bsums[512];

#define QSCALE 0.08838834764831845f   // 1/sqrt(128)

// ---------------- fp16 mma + async copy helpers ----------------
__device__ __forceinline__ void mma16(float* d, const uint32_t* a, const uint32_t* b) {
    asm volatile("mma.sync.aligned.m16n8k16.row.col.f32.f16.f16.f32 "
        "{%0,%1,%2,%3}, {%4,%5,%6,%7}, {%8,%9}, {%0,%1,%2,%3};"
        : "+f"(d[0]), "+f"(d[1]), "+f"(d[2]), "+f"(d[3])
        : "r"(a[0]), "r"(a[1]), "r"(a[2]), "r"(a[3]), "r"(b[0]), "r"(b[1]));
}
__device__ __forceinline__ uint32_t smem_u32(const void* p) {
    uint32_t a;
    asm("{ .reg .u64 t; cvta.to.shared.u64 t, %1; cvt.u32.u64 %0, t; }" : "=r"(a) : "l"(p));
    return a;
}
__device__ __forceinline__ void cp_async16(uint32_t saddr, const void* gptr) {
    asm volatile("cp.async.cg.shared.global [%0], [%1], 16;" :: "r"(saddr), "l"(gptr));
}
#define CP_COMMIT() asm volatile("cp.async.commit_group;" ::: "memory")
#define CP_WAIT(N)  asm volatile("cp.async.wait_group %0;" :: "n"(N) : "memory")

// ---------------- combined packing + graph init + csr zero ----------------
__global__ void pack_all(const float* __restrict__ wq1, const float* __restrict__ bq1,
                         const float* __restrict__ wk1, const float* __restrict__ bk1,
                         const float* __restrict__ wv1, const float* __restrict__ bv1,
                         const float* __restrict__ ws1, const float* __restrict__ bs1,
                         const float* __restrict__ wq2, const float* __restrict__ bq2,
                         const float* __restrict__ wk2, const float* __restrict__ bk2,
                         const float* __restrict__ wv2, const float* __restrict__ bv2,
                         const float* __restrict__ ws2, const float* __restrict__ bs2,
                         const float* __restrict__ gw1, const float* __restrict__ gb1,
                         int n) {
    int idx = blockIdx.x * blockDim.x + threadIdx.x;
    if (idx < 512 * 128) {
        int orow = idx >> 7, k = idx & 127;
        int sel = orow >> 7, r = orow & 127;
        const float* w1 = (sel == 0) ? wq1 : (sel == 1) ? wk1 : (sel == 2) ? wv1 : ws1;
        const float* w2 = (sel == 0) ? wq2 : (sel == 1) ? wk2 : (sel == 2) ? wv2 : ws2;
        float v1 = w1[r * 128 + k], v2 = w2[r * 128 + k];
        if (sel == 0) { v1 *= QSCALE; v2 *= QSCALE; }
        g_Wh1[idx] = __float2half_rn(v1);
        g_Wh2[idx] = __float2half_rn(v2);
    }
    if (idx < 128 * 128) g_Whg[idx] = __float2half_rn(gw1[idx]);
    if (idx < 512) {
        int sel = idx >> 7, r = idx & 127;
        const float* b1 = (sel == 0) ? bq1 : (sel == 1) ? bk1 : (sel == 2) ? bv1 : bs1;
        const float* b2 = (sel == 0) ? bq2 : (sel == 1) ? bk2 : (sel == 2) ? bv2 : bs2;
        float v1 = b1[r], v2 = b2[r];
        if (sel == 0) { v1 *= QSCALE; v2 *= QSCALE; }
        g_B1[idx] = v1; g_B2[idx] = v2;
    }
    if (idx < 128) g_Bg[idx] = gb1[idx];
    if (idx < GGR * 128) g_pool[idx] = 0.f;
    if (idx < GGR) g_gs[idx] = 0.f;
    if (idx < n) g_cur[idx] = 0;            // hist_zero folded in
}

// ---------------- fp16 mma GEMM: X once; cp.async double-buffered W tiles ----------------
#define KH 136
#define SX_BYTES (128 * KH * 2)            // 34816
#define SW_BYTES (64 * KH * 2)             // 17408 per buffer
#define GEMM_SMEM_H (SX_BYTES + 2 * SW_BYTES + 512)

template<bool GATEDOT, int NT, typename TIN>
__global__ __launch_bounds__(256, 2)
void gemm_h(const TIN* __restrict__ X, int n,
            const __half* __restrict__ Wh, const float* __restrict__ bias,
            const float* __restrict__ gw2d, const float* __restrict__ gb2,
            const int* __restrict__ batch) {
    extern __shared__ __half sh[];
    __half* sX = sh;                                   // [128][KH]
    __half* sW = sh + 128 * KH;                        // 2 x [64][KH]
    float* sgate = (float*)(sh + 128 * KH + 2 * 64 * KH);
    const uint32_t sW_u32 = smem_u32(sW);

    const int tid = threadIdx.x, wid = tid >> 5, lane = tid & 31;
    const int wm = wid & 3, wn = wid >> 2;
    const int row0 = blockIdx.x * 128;
    const int grp = lane >> 2, tg = lane & 3;

    if (GATEDOT && tid < 128) sgate[tid] = 0.f;

    // ---- prologue: prefetch W tile 0 ----
#pragma unroll
    for (int j = 0; j < 4; j++) {
        int idx = tid + 256 * j;
        int r = idx >> 4, c8 = idx & 15;
        cp_async16(sW_u32 + (uint32_t)(r * KH + c8 * 8) * 2,
                   Wh + (size_t)r * 128 + c8 * 8);
    }
    CP_COMMIT();

    // ---- X tile (direct loads, overlap with W prefetch) ----
#pragma unroll
    for (int j = 0; j < 8; j++) {
        int idx = tid + 256 * j;
        int r = idx >> 4, c8 = idx & 15;
        int gr = row0 + r;
        uint4 pk = make_uint4(0u, 0u, 0u, 0u);
        if (gr < n) {
            if (sizeof(TIN) == 4) {
                const float* Xf = (const float*)X;
                float4 v0 = *(const float4*)(Xf + (size_t)gr * 128 + c8 * 8);
                float4 v1 = *(const float4*)(Xf + (size_t)gr * 128 + c8 * 8 + 4);
                __half2 h0 = __floats2half2_rn(v0.x, v0.y);
                __half2 h1 = __floats2half2_rn(v0.z, v0.w);
                __half2 h2 = __floats2half2_rn(v1.x, v1.y);
                __half2 h3 = __floats2half2_rn(v1.z, v1.w);
                pk.x = *(uint32_t*)&h0; pk.y = *(uint32_t*)&h1;
                pk.z = *(uint32_t*)&h2; pk.w = *(uint32_t*)&h3;
            } else {
                const __half* Xh = (const __half*)X;
                pk = *(const uint4*)(Xh + (size_t)gr * 128 + c8 * 8);
            }
        }
        *(uint4*)(sX + r * KH + c8 * 8) = pk;
    }

    float rp[2][2] = {{0.f, 0.f}, {0.f, 0.f}};

    for (int t = 0; t < NT; t++) {
        // prefetch next tile into the other buffer (after prior iter's closing sync)
        if (t + 1 < NT) {
            const int col1 = (t + 1) * 64;
            const uint32_t bufoff = (uint32_t)(((t + 1) & 1) * 64 * KH) * 2;
#pragma unroll
            for (int j = 0; j < 4; j++) {
                int idx = tid + 256 * j;
                int r = idx >> 4, c8 = idx & 15;
                cp_async16(sW_u32 + bufoff + (uint32_t)(r * KH + c8 * 8) * 2,
                           Wh + (size_t)(col1 + r) * 128 + c8 * 8);
            }
            CP_COMMIT();
            CP_WAIT(1);     // tile t complete
        } else {
            CP_WAIT(0);
        }
        __syncthreads();

        const __half* sWt = sW + (t & 1) * 64 * KH;
        const int col0 = t * 64;

        float acc[2][4][4];
#pragma unroll
        for (int mt = 0; mt < 2; mt++)
#pragma unroll
            for (int nt = 0; nt < 4; nt++)
#pragma unroll
                for (int q = 0; q < 4; q++) acc[mt][nt][q] = 0.f;

#pragma unroll
        for (int ks = 0; ks < 8; ks++) {
            const int c = ks * 16 + 2 * tg;
            uint32_t a[2][4];
#pragma unroll
            for (int mt = 0; mt < 2; mt++) {
                const int r = wm * 32 + mt * 16 + grp;
                a[mt][0] = *(const uint32_t*)(sX + r * KH + c);
                a[mt][1] = *(const uint32_t*)(sX + (r + 8) * KH + c);
                a[mt][2] = *(const uint32_t*)(sX + r * KH + c + 8);
                a[mt][3] = *(const uint32_t*)(sX + (r + 8) * KH + c + 8);
            }
            uint32_t b[4][2];
#pragma unroll
            for (int nt = 0; nt < 4; nt++) {
                const int nr = wn * 32 + nt * 8 + grp;
                b[nt][0] = *(const uint32_t*)(sWt + nr * KH + c);
                b[nt][1] = *(const uint32_t*)(sWt + nr * KH + c + 8);
            }
#pragma unroll
            for (int mt = 0; mt < 2; mt++)
#pragma unroll
                for (int nt = 0; nt < 4; nt++) mma16(acc[mt][nt], a[mt], b[nt]);
        }

        // ---- epilogue for this tile ----
#pragma unroll
        for (int mt = 0; mt < 2; mt++) {
            const int gr = row0 + wm * 32 + mt * 16 + grp;
#pragma unroll
            for (int nt = 0; nt < 4; nt++) {
                const int col = col0 + wn * 32 + nt * 8 + 2 * tg;
                const float b0 = bias[col], b1 = bias[col + 1];
                float2 o1 = make_float2(acc[mt][nt][0] + b0, acc[mt][nt][1] + b1);
                float2 o2 = make_float2(acc[mt][nt][2] + b0, acc[mt][nt][3] + b1);
                if (GATEDOT) {
                    o1.x = fmaxf(o1.x, 0.f); o1.y = fmaxf(o1.y, 0.f);
                    o2.x = fmaxf(o2.x, 0.f); o2.y = fmaxf(o2.y, 0.f);
                    const float w0 = gw2d[col], w1 = gw2d[col + 1];
                    rp[mt][0] += o1.x * w0 + o1.y * w1;
                    rp[mt][1] += o2.x * w0 + o2.y * w1;
                } else {
                    __half* dst0;
                    __half* dst1;
                    if (t < 2) {
                        dst0 = g_q16 + (size_t)gr * 128 + col;
                        dst1 = g_q16 + (size_t)(gr + 8) * 128 + col;
                    } else if (t < 6) {
                        dst0 = g_kv16 + (size_t)gr * 256 + (col - 128);
                        dst1 = g_kv16 + (size_t)(gr + 8) * 256 + (col - 128);
                    } else {
                        dst0 = g_sk16 + (size_t)gr * 128 + (col - 384);
                        dst1 = g_sk16 + (size_t)(gr + 8) * 128 + (col - 384);
                    }
                    if (gr < n)     *(__half2*)dst0 = __floats2half2_rn(o1.x, o1.y);
                    if (gr + 8 < n) *(__half2*)dst1 = __floats2half2_rn(o2.x, o2.y);
                }
            }
        }
        __syncthreads();   // all warps done with buf[t&1] before it is refilled
    }

    if (GATEDOT) {
#pragma unroll
        for (int mt = 0; mt < 2; mt++)
#pragma unroll
            for (int h = 0; h < 2; h++) {
                float v = rp[mt][h];
                v += __shfl_xor_sync(0xffffffffu, v, 1);
                v += __shfl_xor_sync(0xffffffffu, v, 2);
                if (tg == 0)
                    atomicAdd(&sgate[wm * 32 + mt * 16 + grp + h * 8], v);
            }
        __syncthreads();
        if (tid < 128) {
            const int row = row0 + tid;
            if (row < n) {
                float ev = __expf(sgate[tid] + gb2[0]);
                g_gate[row] = ev;
                atomicAdd(&g_gs[batch[row]], ev);
            }
        }
    }
}

// ================= CSR build =================
__global__ void hist(const int* __restrict__ dst, int E) {
    int e = blockIdx.x * blockDim.x + threadIdx.x;
    if (e < E) atomicAdd(&g_cur[dst[e]], 1);
}
__global__ void scan_blocks(int n) {
    __shared__ int sm[256];
    int t = threadIdx.x;
    int i = blockIdx.x * 256 + t;
    int v = (i < n) ? g_cur[i] : 0;
    sm[t] = v;
    __syncthreads();
#pragma unroll
    for (int o = 1; o < 256; o <<= 1) {
        int x = (t >= o) ? sm[t - o] : 0;
        __syncthreads();
        sm[t] += x;
        __syncthreads();
    }
    if (i < n) g_off[i] = sm[t] - v;
    if (t == 255) g_bsums[blockIdx.x] = sm[255];
}
__global__ void scan_tops(int nblk) {
    __shared__ int sm[512];
    int t = threadIdx.x;
    int v = (t < nblk) ? g_bsums[t] : 0;
    sm[t] = v;
    __syncthreads();
#pragma unroll
    for (int o = 1; o < 512; o <<= 1) {
        int x = (t >= o) ? sm[t - o] : 0;
        __syncthreads();
        sm[t] += x;
        __syncthreads();
    }
    if (t < nblk) g_bsums[t] = sm[t] - v;
}
__global__ void scan_add(int n, int E) {
    int i = blockIdx.x * 256 + threadIdx.x;
    if (i < n) {
        int o = g_off[i] + g_bsums[blockIdx.x];
        g_off[i] = o;
        g_cur[i] = o;
    }
    if (i == 0) g_off[n] = E;
}
__global__ void fill_csr(const int* __restrict__ src, const int* __restrict__ dst, int E) {
    int e = blockIdx.x * blockDim.x + threadIdx.x;
    if (e >= E) return;
    int p = atomicAdd(&g_cur[dst[e]], 1);
    g_csrc[p] = src[e];
}

// ================= fused per-node attention (proven shape) =================
__global__ __launch_bounds__(256, 6)
void node_attn(int n) {
    int node = (blockIdx.x * blockDim.x + threadIdx.x) >> 5;
    int lane = threadIdx.x & 31;
    if (node >= n) return;

    uint2 qp = *(const uint2*)(g_q16 + (size_t)node * 128 + lane * 4);
    float2 q01 = __half22float2(*(const __half2*)&qp.x);
    float2 q23 = __half22float2(*(const __half2*)&qp.y);
    float4 q = make_float4(q01.x, q01.y, q23.x, q23.y);

    int beg = g_off[node], end = g_off[node + 1];
    float4 acc = make_float4(0.f, 0.f, 0.f, 0.f);
    float sum = 0.f;

    int j = beg;
    for (; j + 4 <= end; j += 4) {
        const __half* r[4];
#pragma unroll
        for (int u = 0; u < 4; u++) r[u] = g_kv16 + (size_t)g_csrc[j + u] * 256;
        uint2 kk[4], vv[4];
#pragma unroll
        for (int u = 0; u < 4; u++) kk[u] = *(const uint2*)(r[u] + lane * 4);
#pragma unroll
        for (int u = 0; u < 4; u++) vv[u] = *(const uint2*)(r[u] + 128 + lane * 4);

        float d[4];
#pragma unroll
        for (int u = 0; u < 4; u++) {
            float2 a = __half22float2(*(const __half2*)&kk[u].x);
            float2 b = __half22float2(*(const __half2*)&kk[u].y);
            d[u] = q.x * a.x + q.y * a.y + q.z * b.x + q.w * b.y;
        }
#pragma unroll
        for (int o = 16; o; o >>= 1) {
#pragma unroll
            for (int u = 0; u < 4; u++) d[u] += __shfl_xor_sync(0xffffffffu, d[u], o);
        }
#pragma unroll
        for (int u = 0; u < 4; u++) {
            float e = __expf(d[u]);
            float2 va = __half22float2(*(const __half2*)&vv[u].x);
            float2 vb = __half22float2(*(const __half2*)&vv[u].y);
            acc.x += e * va.x; acc.y += e * va.y;
            acc.z += e * vb.x; acc.w += e * vb.y;
            sum += e;
        }
    }
    for (; j < end; j++) {
        const __half* r0 = g_kv16 + (size_t)g_csrc[j] * 256;
        uint2 kk = *(const uint2*)(r0 + lane * 4);
        uint2 vv = *(const uint2*)(r0 + 128 + lane * 4);
        float2 a = __half22float2(*(const __half2*)&kk.x);
        float2 b = __half22float2(*(const __half2*)&kk.y);
        float d0 = q.x * a.x + q.y * a.y + q.z * b.x + q.w * b.y;
#pragma unroll
        for (int o = 16; o; o >>= 1) d0 += __shfl_xor_sync(0xffffffffu, d0, o);
        float e0 = __expf(d0);
        float2 va = __half22float2(*(const __half2*)&vv.x);
        float2 vb = __half22float2(*(const __half2*)&vv.y);
        acc.x += e0 * va.x; acc.y += e0 * va.y;
        acc.z += e0 * vb.x; acc.w += e0 * vb.y;
        sum += e0;
    }

    float inv = (end > beg) ? (1.f / sum) : 0.f;
    uint2 sp = *(const uint2*)(g_sk16 + (size_t)node * 128 + lane * 4);
    float2 s01 = __half22float2(*(const __half2*)&sp.x);
    float2 s23 = __half22float2(*(const __half2*)&sp.y);
    float ox = fmaxf(acc.x * inv + s01.x, 0.f);
    float oy = fmaxf(acc.y * inv + s01.y, 0.f);
    float oz = fmaxf(acc.z * inv + s23.x, 0.f);
    float ow = fmaxf(acc.w * inv + s23.y, 0.f);
    uint2 outp;
    *(__half2*)&outp.x = __floats2half2_rn(ox, oy);
    *(__half2*)&outp.y = __floats2half2_rn(oz, ow);
    *(uint2*)(g_h16 + (size_t)node * 128 + lane * 4) = outp;
}

// ---------------- graph-level ----------------
#define POOL_CHUNK 512
__global__ void pool_kernel(const int* __restrict__ batch, int n) {
    int d = threadIdx.x;
    int n0 = blockIdx.x * POOL_CHUNK;
    int n1 = min(n0 + POOL_CHUNK, n);
    if (n0 >= n) return;
    int curb = batch[n0];
    float acc = 0.f;
    for (int node = n0; node < n1; node++) {
        int b = batch[node];
        if (b != curb) {
            atomicAdd(&g_pool[curb * 128 + d], acc);
            acc = 0.f; curb = b;
        }
        float wgt = g_gate[node] / g_gs[b];
        acc += wgt * __half2float(g_h16[(size_t)node * 128 + d]);
    }
    atomicAdd(&g_pool[curb * 128 + d], acc);
}

__global__ void classifier(const float* __restrict__ cw, const float* __restrict__ cb,
                           float* __restrict__ out) {
    int i = threadIdx.x;
    if (i >= GGR * 10) return;
    int g = i / 10, c = i % 10;
    float a = cb[c];
#pragma unroll 16
    for (int k = 0; k < 128; k++) a += g_pool[g * 128 + k] * cw[c * 128 + k];
    out[i] = a;
}

// ---------------- host orchestration ----------------
extern "C" void kernel_launch(void* const* d_in, const int* in_sizes, int n_in,
                              void* d_out, int out_size) {
    const float* x   = (const float*)d_in[0];
    const int* eidx  = (const int*)d_in[1];
    const int* batch = (const int*)d_in[2];
    const float *wq1 = (const float*)d_in[3],  *bq1 = (const float*)d_in[4];
    const float *wk1 = (const float*)d_in[5],  *bk1 = (const float*)d_in[6];
    const float *wv1 = (const float*)d_in[7],  *bv1 = (const float*)d_in[8];
    const float *ws1 = (const float*)d_in[9],  *bs1 = (const float*)d_in[10];
    const float *wq2 = (const float*)d_in[11], *bq2 = (const float*)d_in[12];
    const float *wk2 = (const float*)d_in[13], *bk2 = (const float*)d_in[14];
    const float *wv2 = (const float*)d_in[15], *bv2 = (const float*)d_in[16];
    const float *ws2 = (const float*)d_in[17], *bs2 = (const float*)d_in[18];
    const float *gw1 = (const float*)d_in[19], *gb1 = (const float*)d_in[20];
    const float *gw2 = (const float*)d_in[21], *gb2 = (const float*)d_in[22];
    const float *cw  = (const float*)d_in[23], *cb  = (const float*)d_in[24];
    float* out = (float*)d_out;

    const int n = in_sizes[0] / 128;
    const int E = in_sizes[1] / 2;
    const int* src = eidx;
    const int* dst = eidx + E;

    static __half *p_h16 = nullptr, *p_Wh1 = nullptr, *p_Wh2 = nullptr, *p_Whg = nullptr;
    static float  *p_B1 = nullptr,  *p_B2 = nullptr,  *p_Bg = nullptr;
    if (!p_h16) {
        cudaGetSymbolAddress((void**)&p_h16,  g_h16);
        cudaGetSymbolAddress((void**)&p_Wh1,  g_Wh1);
        cudaGetSymbolAddress((void**)&p_Wh2,  g_Wh2);
        cudaGetSymbolAddress((void**)&p_Whg,  g_Whg);
        cudaGetSymbolAddress((void**)&p_B1,   g_B1);
        cudaGetSymbolAddress((void**)&p_B2,   g_B2);
        cudaGetSymbolAddress((void**)&p_Bg,   g_Bg);
        cudaFuncSetAttribute((const void*)gemm_h<false, 8, float>,
                             cudaFuncAttributeMaxDynamicSharedMemorySize, GEMM_SMEM_H);
        cudaFuncSetAttribute((const void*)gemm_h<false, 8, __half>,
                             cudaFuncAttributeMaxDynamicSharedMemorySize, GEMM_SMEM_H);
        cudaFuncSetAttribute((const void*)gemm_h<true, 2, __half>,
                             cudaFuncAttributeMaxDynamicSharedMemorySize, GEMM_SMEM_H);
    }

    const int etb  = (E + 255) / 256;
    const int nblk = (n + 255) / 256;
    const int nab  = (n * 32 + 255) / 256;      // 1 warp/node
    const int mtiles = (n + 127) / 128;

    // ---- combined packs + graph init + csr-counter zero ----
    pack_all<<<nblk, 256>>>(wq1, bq1, wk1, bk1, wv1, bv1, ws1, bs1,
                            wq2, bq2, wk2, bk2, wv2, bv2, ws2, bs2,
                            gw1, gb1, n);

    // ---- CSR build ----
    hist<<<etb, 256>>>(dst, E);
    scan_blocks<<<nblk, 256>>>(n);
    scan_tops<<<1, 512>>>(nblk);
    scan_add<<<nblk, 256>>>(n, E);
    fill_csr<<<etb, 256>>>(src, dst, E);

    // ---- Layer 1 (fp32 input) ----
    gemm_h<false, 8, float><<<mtiles, 256, GEMM_SMEM_H>>>(x, n, p_Wh1, p_B1,
                                                          nullptr, nullptr, nullptr);
    node_attn<<<nab, 256>>>(n);

    // ---- Layer 2 (fp16 input) ----
    gemm_h<false, 8, __half><<<mtiles, 256, GEMM_SMEM_H>>>(p_h16, n, p_Wh2, p_B2,
                                                           nullptr, nullptr, nullptr);
    node_attn<<<nab, 256>>>(n);

    // ---- Global attention (gate dot + exp + graph sums fused into GEMM) ----
    gemm_h<true, 2, __half><<<mtiles, 256, GEMM_SMEM_H>>>(p_h16, n, p_Whg, p_Bg,
                                                          gw2, gb2, batch);
    pool_kernel<<<(n + POOL_CHUNK - 1) / POOL_CHUNK, 128>>>(batch, n);

    // ---- Classifier ----
    classifier<<<1, 1024>>>(cw, cb, out);
}

// round 17
// speedup vs baseline: 1.4968x; 1.0611x over previous
#include <cuda_runtime.h>
#include <cuda_fp16.h>
#include <cstdint>

// Problem constants
#define NN 100000
#define EE 1600000
#define GGR 64

// ---------------- static device scratch (all intermediates fp16) ----------------
__device__ __align__(16) __half g_q16 [(size_t)NN * 128];  // q, pre-scaled by 1/sqrt(128)
__device__ __align__(16) __half g_kv16[(size_t)NN * 256];  // k[0:128) v[128:256)
__device__ __align__(16) __half g_sk16[(size_t)NN * 128];  // skip connection
__device__ __align__(16) __half g_h16 [(size_t)NN * 128];  // layer output
__device__ float    g_gate[NN];                // exp(gate logit)
__device__ float    g_pool[GGR * 128];
__device__ float    g_gs[GGR];
__device__ __align__(16) __half g_Wh1[512 * 128];
__device__ __align__(16) __half g_Wh2[512 * 128];
__device__ __align__(16) __half g_Whg[128 * 128];
__device__ float    g_B1[512];
__device__ float    g_B2[512];
__device__ float    g_Bg[128];
// CSR (dst-sorted adjacency)
__device__ int      g_off[NN + 1];
__device__ int      g_cur[NN];
__device__ int      g_csrc[EE];
__device__ int      g_bsums[512];

#define QSCALE 0.08838834764831845f   // 1/sqrt(128)

// ---------------- fp16 mma helpers ----------------
__device__ __forceinline__ void mma16(float* d, const uint32_t* a, const uint32_t* b) {
    asm volatile("mma.sync.aligned.m16n8k16.row.col.f32.f16.f16.f32 "
        "{%0,%1,%2,%3}, {%4,%5,%6,%7}, {%8,%9}, {%0,%1,%2,%3};"
        : "+f"(d[0]), "+f"(d[1]), "+f"(d[2]), "+f"(d[3])
        : "r"(a[0]), "r"(a[1]), "r"(a[2]), "r"(a[3]), "r"(b[0]), "r"(b[1]));
}

// ---------------- combined packing + graph init + csr zero ----------------
__global__ void pack_all(const float* __restrict__ wq1, const float* __restrict__ bq1,
                         const float* __restrict__ wk1, const float* __restrict__ bk1,
                         const float* __restrict__ wv1, const float* __restrict__ bv1,
                         const float* __restrict__ ws1, const float* __restrict__ bs1,
                         const float* __restrict__ wq2, const float* __restrict__ bq2,
                         const float* __restrict__ wk2, const float* __restrict__ bk2,
                         const float* __restrict__ wv2, const float* __restrict__ bv2,
                         const float* __restrict__ ws2, const float* __restrict__ bs2,
                         const float* __restrict__ gw1, const float* __restrict__ gb1,
                         int n) {
    int idx = blockIdx.x * blockDim.x + threadIdx.x;
    if (idx < 512 * 128) {
        int orow = idx >> 7, k = idx & 127;
        int sel = orow >> 7, r = orow & 127;
        const float* w1 = (sel == 0) ? wq1 : (sel == 1) ? wk1 : (sel == 2) ? wv1 : ws1;
        const float* w2 = (sel == 0) ? wq2 : (sel == 1) ? wk2 : (sel == 2) ? wv2 : ws2;
        float v1 = w1[r * 128 + k], v2 = w2[r * 128 + k];
        if (sel == 0) { v1 *= QSCALE; v2 *= QSCALE; }
        g_Wh1[idx] = __float2half_rn(v1);
        g_Wh2[idx] = __float2half_rn(v2);
    }
    if (idx < 128 * 128) g_Whg[idx] = __float2half_rn(gw1[idx]);
    if (idx < 512) {
        int sel = idx >> 7, r = idx & 127;
        const float* b1 = (sel == 0) ? bq1 : (sel == 1) ? bk1 : (sel == 2) ? bv1 : bs1;
        const float* b2 = (sel == 0) ? bq2 : (sel == 1) ? bk2 : (sel == 2) ? bv2 : bs2;
        float v1 = b1[r], v2 = b2[r];
        if (sel == 0) { v1 *= QSCALE; v2 *= QSCALE; }
        g_B1[idx] = v1; g_B2[idx] = v2;
    }
    if (idx < 128) g_Bg[idx] = gb1[idx];
    if (idx < GGR * 128) g_pool[idx] = 0.f;
    if (idx < GGR) g_gs[idx] = 0.f;
    if (idx < n) g_cur[idx] = 0;            // hist_zero folded in
}

// ---------------- fp16 mma GEMM: X once; staged coalesced epilogue ----------------
#define KH 136
#define OSTR 72                              // staging stride (halves), conflict-free
#define SX_HALVES (128 * KH)
#define SW_HALVES (64 * KH)
#define SO_HALVES (128 * OSTR)
#define GEMM_SMEM_H ((SX_HALVES + SW_HALVES + SO_HALVES) * 2 + 512)

template<bool GATEDOT, int NT, typename TIN>
__global__ __launch_bounds__(256, 2)
void gemm_h(const TIN* __restrict__ X, int n,
            const __half* __restrict__ Wh, const float* __restrict__ bias,
            const float* __restrict__ gw2d, const float* __restrict__ gb2,
            const int* __restrict__ batch) {
    extern __shared__ __half sh[];
    __half* sX = sh;                          // [128][KH]
    __half* sW = sh + SX_HALVES;              // [64][KH]
    __half* sO = sh + SX_HALVES + SW_HALVES;  // [128][OSTR] staging
    float* sgate = (float*)(sO + SO_HALVES);

    const int tid = threadIdx.x, wid = tid >> 5, lane = tid & 31;
    const int wm = wid & 3, wn = wid >> 2;
    const int row0 = blockIdx.x * 128;
    const int grp = lane >> 2, tg = lane & 3;

    if (GATEDOT && tid < 128) sgate[tid] = 0.f;

    // ---- X tile loaded ONCE ----
#pragma unroll
    for (int j = 0; j < 8; j++) {
        int idx = tid + 256 * j;
        int r = idx >> 4, c8 = idx & 15;
        int gr = row0 + r;
        uint4 pk = make_uint4(0u, 0u, 0u, 0u);
        if (gr < n) {
            if (sizeof(TIN) == 4) {
                const float* Xf = (const float*)X;
                float4 v0 = *(const float4*)(Xf + (size_t)gr * 128 + c8 * 8);
                float4 v1 = *(const float4*)(Xf + (size_t)gr * 128 + c8 * 8 + 4);
                __half2 h0 = __floats2half2_rn(v0.x, v0.y);
                __half2 h1 = __floats2half2_rn(v0.z, v0.w);
                __half2 h2 = __floats2half2_rn(v1.x, v1.y);
                __half2 h3 = __floats2half2_rn(v1.z, v1.w);
                pk.x = *(uint32_t*)&h0; pk.y = *(uint32_t*)&h1;
                pk.z = *(uint32_t*)&h2; pk.w = *(uint32_t*)&h3;
            } else {
                const __half* Xh = (const __half*)X;
                pk = *(const uint4*)(Xh + (size_t)gr * 128 + c8 * 8);
            }
        }
        *(uint4*)(sX + r * KH + c8 * 8) = pk;
    }

    float rp[2][2] = {{0.f, 0.f}, {0.f, 0.f}};

    for (int t = 0; t < NT; t++) {
        const int col0 = t * 64;
        // ---- W tile ----
#pragma unroll
        for (int j = 0; j < 4; j++) {
            int idx = tid + 256 * j;
            int r = idx >> 4, c8 = idx & 15;
            *(uint4*)(sW + r * KH + c8 * 8) =
                *(const uint4*)(Wh + (size_t)(col0 + r) * 128 + c8 * 8);
        }
        __syncthreads();

        float acc[2][4][4];
#pragma unroll
        for (int mt = 0; mt < 2; mt++)
#pragma unroll
            for (int nt = 0; nt < 4; nt++)
#pragma unroll
                for (int q = 0; q < 4; q++) acc[mt][nt][q] = 0.f;

#pragma unroll
        for (int ks = 0; ks < 8; ks++) {
            const int c = ks * 16 + 2 * tg;
            uint32_t a[2][4];
#pragma unroll
            for (int mt = 0; mt < 2; mt++) {
                const int r = wm * 32 + mt * 16 + grp;
                a[mt][0] = *(const uint32_t*)(sX + r * KH + c);
                a[mt][1] = *(const uint32_t*)(sX + (r + 8) * KH + c);
                a[mt][2] = *(const uint32_t*)(sX + r * KH + c + 8);
                a[mt][3] = *(const uint32_t*)(sX + (r + 8) * KH + c + 8);
            }
            uint32_t b[4][2];
#pragma unroll
            for (int nt = 0; nt < 4; nt++) {
                const int nr = wn * 32 + nt * 8 + grp;
                b[nt][0] = *(const uint32_t*)(sW + nr * KH + c);
                b[nt][1] = *(const uint32_t*)(sW + nr * KH + c + 8);
            }
#pragma unroll
            for (int mt = 0; mt < 2; mt++)
#pragma unroll
                for (int nt = 0; nt < 4; nt++) mma16(acc[mt][nt], a[mt], b[nt]);
        }

        // ---- epilogue: bias(+relu) into staging (conflict-free) or gate partials ----
#pragma unroll
        for (int mt = 0; mt < 2; mt++) {
            const int r0l = wm * 32 + mt * 16 + grp;
#pragma unroll
            for (int nt = 0; nt < 4; nt++) {
                const int col = col0 + wn * 32 + nt * 8 + 2 * tg;
                const float b0 = bias[col], b1 = bias[col + 1];
                float2 o1 = make_float2(acc[mt][nt][0] + b0, acc[mt][nt][1] + b1);
                float2 o2 = make_float2(acc[mt][nt][2] + b0, acc[mt][nt][3] + b1);
                if (GATEDOT) {
                    o1.x = fmaxf(o1.x, 0.f); o1.y = fmaxf(o1.y, 0.f);
                    o2.x = fmaxf(o2.x, 0.f); o2.y = fmaxf(o2.y, 0.f);
                    const float w0 = gw2d[col], w1 = gw2d[col + 1];
                    rp[mt][0] += o1.x * w0 + o1.y * w1;
                    rp[mt][1] += o2.x * w0 + o2.y * w1;
                } else {
                    const int lc = col - col0;
                    *(__half2*)(sO + r0l * OSTR + lc) = __floats2half2_rn(o1.x, o1.y);
                    *(__half2*)(sO + (r0l + 8) * OSTR + lc) = __floats2half2_rn(o2.x, o2.y);
                }
            }
        }
        __syncthreads();

        // ---- coalesced copy-out: 1024 uint4 = 128 rows x 64 cols ----
        if (!GATEDOT) {
#pragma unroll
            for (int it = 0; it < 4; it++) {
                int idx = tid + it * 256;
                int r = idx >> 3, c8 = idx & 7;
                int gr = row0 + r;
                if (gr < n) {
                    uint4 v = *(const uint4*)(sO + r * OSTR + c8 * 8);
                    __half* dstp;
                    if (t < 2)      dstp = g_q16 + (size_t)gr * 128 + col0 + c8 * 8;
                    else if (t < 6) dstp = g_kv16 + (size_t)gr * 256 + (col0 - 128) + c8 * 8;
                    else            dstp = g_sk16 + (size_t)gr * 128 + (col0 - 384) + c8 * 8;
                    *(uint4*)dstp = v;
                }
            }
        }
        __syncthreads();   // protect sW and sO before next tile
    }

    if (GATEDOT) {
#pragma unroll
        for (int mt = 0; mt < 2; mt++)
#pragma unroll
            for (int h = 0; h < 2; h++) {
                float v = rp[mt][h];
                v += __shfl_xor_sync(0xffffffffu, v, 1);
                v += __shfl_xor_sync(0xffffffffu, v, 2);
                if (tg == 0)
                    atomicAdd(&sgate[wm * 32 + mt * 16 + grp + h * 8], v);
            }
        __syncthreads();
        if (tid < 128) {
            const int row = row0 + tid;
            if (row < n) {
                float ev = __expf(sgate[tid] + gb2[0]);
                g_gate[row] = ev;
                atomicAdd(&g_gs[batch[row]], ev);
            }
        }
    }
}

// ================= CSR build =================
__global__ void hist(const int* __restrict__ dst, int E) {
    int e = blockIdx.x * blockDim.x + threadIdx.x;
    if (e < E) atomicAdd(&g_cur[dst[e]], 1);
}
__global__ void scan_blocks(int n) {
    __shared__ int sm[256];
    int t = threadIdx.x;
    int i = blockIdx.x * 256 + t;
    int v = (i < n) ? g_cur[i] : 0;
    sm[t] = v;
    __syncthreads();
#pragma unroll
    for (int o = 1; o < 256; o <<= 1) {
        int x = (t >= o) ? sm[t - o] : 0;
        __syncthreads();
        sm[t] += x;
        __syncthreads();
    }
    if (i < n) g_off[i] = sm[t] - v;
    if (t == 255) g_bsums[blockIdx.x] = sm[255];
}
__global__ void scan_tops(int nblk) {
    __shared__ int sm[512];
    int t = threadIdx.x;
    int v = (t < nblk) ? g_bsums[t] : 0;
    sm[t] = v;
    __syncthreads();
#pragma unroll
    for (int o = 1; o < 512; o <<= 1) {
        int x = (t >= o) ? sm[t - o] : 0;
        __syncthreads();
        sm[t] += x;
        __syncthreads();
    }
    if (t < nblk) g_bsums[t] = sm[t] - v;
}
__global__ void scan_add(int n, int E) {
    int i = blockIdx.x * 256 + threadIdx.x;
    if (i < n) {
        int o = g_off[i] + g_bsums[blockIdx.x];
        g_off[i] = o;
        g_cur[i] = o;
    }
    if (i == 0) g_off[n] = E;
}
__global__ void fill_csr(const int* __restrict__ src, const int* __restrict__ dst, int E) {
    int e = blockIdx.x * blockDim.x + threadIdx.x;
    if (e >= E) return;
    int p = atomicAdd(&g_cur[dst[e]], 1);
    g_csrc[p] = src[e];
}

// ================= fused per-node attention (proven shape) =================
__global__ __launch_bounds__(256, 6)
void node_attn(int n) {
    int node = (blockIdx.x * blockDim.x + threadIdx.x) >> 5;
    int lane = threadIdx.x & 31;
    if (node >= n) return;

    uint2 qp = *(const uint2*)(g_q16 + (size_t)node * 128 + lane * 4);
    float2 q01 = __half22float2(*(const __half2*)&qp.x);
    float2 q23 = __half22float2(*(const __half2*)&qp.y);
    float4 q = make_float4(q01.x, q01.y, q23.x, q23.y);

    int beg = g_off[node], end = g_off[node + 1];
    float4 acc = make_float4(0.f, 0.f, 0.f, 0.f);
    float sum = 0.f;

    int j = beg;
    for (; j + 4 <= end; j += 4) {
        const __half* r[4];
#pragma unroll
        for (int u = 0; u < 4; u++) r[u] = g_kv16 + (size_t)g_csrc[j + u] * 256;
        uint2 kk[4], vv[4];
#pragma unroll
        for (int u = 0; u < 4; u++) kk[u] = *(const uint2*)(r[u] + lane * 4);
#pragma unroll
        for (int u = 0; u < 4; u++) vv[u] = *(const uint2*)(r[u] + 128 + lane * 4);

        float d[4];
#pragma unroll
        for (int u = 0; u < 4; u++) {
            float2 a = __half22float2(*(const __half2*)&kk[u].x);
            float2 b = __half22float2(*(const __half2*)&kk[u].y);
            d[u] = q.x * a.x + q.y * a.y + q.z * b.x + q.w * b.y;
        }
#pragma unroll
        for (int o = 16; o; o >>= 1) {
#pragma unroll
            for (int u = 0; u < 4; u++) d[u] += __shfl_xor_sync(0xffffffffu, d[u], o);
        }
#pragma unroll
        for (int u = 0; u < 4; u++) {
            float e = __expf(d[u]);
            float2 va = __half22float2(*(const __half2*)&vv[u].x);
            float2 vb = __half22float2(*(const __half2*)&vv[u].y);
            acc.x += e * va.x; acc.y += e * va.y;
            acc.z += e * vb.x; acc.w += e * vb.y;
            sum += e;
        }
    }
    for (; j < end; j++) {
        const __half* r0 = g_kv16 + (size_t)g_csrc[j] * 256;
        uint2 kk = *(const uint2*)(r0 + lane * 4);
        uint2 vv = *(const uint2*)(r0 + 128 + lane * 4);
        float2 a = __half22float2(*(const __half2*)&kk.x);
        float2 b = __half22float2(*(const __half2*)&kk.y);
        float d0 = q.x * a.x + q.y * a.y + q.z * b.x + q.w * b.y;
#pragma unroll
        for (int o = 16; o; o >>= 1) d0 += __shfl_xor_sync(0xffffffffu, d0, o);
        float e0 = __expf(d0);
        float2 va = __half22float2(*(const __half2*)&vv.x);
        float2 vb = __half22float2(*(const __half2*)&vv.y);
        acc.x += e0 * va.x; acc.y += e0 * va.y;
        acc.z += e0 * vb.x; acc.w += e0 * vb.y;
        sum += e0;
    }

    float inv = (end > beg) ? (1.f / sum) : 0.f;
    uint2 sp = *(const uint2*)(g_sk16 + (size_t)node * 128 + lane * 4);
    float2 s01 = __half22float2(*(const __half2*)&sp.x);
    float2 s23 = __half22float2(*(const __half2*)&sp.y);
    float ox = fmaxf(acc.x * inv + s01.x, 0.f);
    float oy = fmaxf(acc.y * inv + s01.y, 0.f);
    float oz = fmaxf(acc.z * inv + s23.x, 0.f);
    float ow = fmaxf(acc.w * inv + s23.y, 0.f);
    uint2 outp;
    *(__half2*)&outp.x = __floats2half2_rn(ox, oy);
    *(__half2*)&outp.y = __floats2half2_rn(oz, ow);
    *(uint2*)(g_h16 + (size_t)node * 128 + lane * 4) = outp;
}

// ---------------- graph-level ----------------
#define POOL_CHUNK 512
__global__ void pool_kernel(const int* __restrict__ batch, int n) {
    int d = threadIdx.x;
    int n0 = blockIdx.x * POOL_CHUNK;
    int n1 = min(n0 + POOL_CHUNK, n);
    if (n0 >= n) return;
    int curb = batch[n0];
    float acc = 0.f;
    for (int node = n0; node < n1; node++) {
        int b = batch[node];
        if (b != curb) {
            atomicAdd(&g_pool[curb * 128 + d], acc);
            acc = 0.f; curb = b;
        }
        float wgt = g_gate[node] / g_gs[b];
        acc += wgt * __half2float(g_h16[(size_t)node * 128 + d]);
    }
    atomicAdd(&g_pool[curb * 128 + d], acc);
}

__global__ void classifier(const float* __restrict__ cw, const float* __restrict__ cb,
                           float* __restrict__ out) {
    int i = threadIdx.x;
    if (i >= GGR * 10) return;
    int g = i / 10, c = i % 10;
    float a = cb[c];
#pragma unroll 16
    for (int k = 0; k < 128; k++) a += g_pool[g * 128 + k] * cw[c * 128 + k];
    out[i] = a;
}

// ---------------- host orchestration ----------------
extern "C" void kernel_launch(void* const* d_in, const int* in_sizes, int n_in,
                              void* d_out, int out_size) {
    const float* x   = (const float*)d_in[0];
    const int* eidx  = (const int*)d_in[1];
    const int* batch = (const int*)d_in[2];
    const float *wq1 = (const float*)d_in[3],  *bq1 = (const float*)d_in[4];
    const float *wk1 = (const float*)d_in[5],  *bk1 = (const float*)d_in[6];
    const float *wv1 = (const float*)d_in[7],  *bv1 = (const float*)d_in[8];
    const float *ws1 = (const float*)d_in[9],  *bs1 = (const float*)d_in[10];
    const float *wq2 = (const float*)d_in[11], *bq2 = (const float*)d_in[12];
    const float *wk2 = (const float*)d_in[13], *bk2 = (const float*)d_in[14];
    const float *wv2 = (const float*)d_in[15], *bv2 = (const float*)d_in[16];
    const float *ws2 = (const float*)d_in[17], *bs2 = (const float*)d_in[18];
    const float *gw1 = (const float*)d_in[19], *gb1 = (const float*)d_in[20];
    const float *gw2 = (const float*)d_in[21], *gb2 = (const float*)d_in[22];
    const float *cw  = (const float*)d_in[23], *cb  = (const float*)d_in[24];
    float* out = (float*)d_out;

    const int n = in_sizes[0] / 128;
    const int E = in_sizes[1] / 2;
    const int* src = eidx;
    const int* dst = eidx + E;

    static __half *p_h16 = nullptr, *p_Wh1 = nullptr, *p_Wh2 = nullptr, *p_Whg = nullptr;
    static float  *p_B1 = nullptr,  *p_B2 = nullptr,  *p_Bg = nullptr;
    static cudaStream_t s1 = nullptr;
    static cudaEvent_t evFork = nullptr, evCsr = nullptr;
    if (!p_h16) {
        cudaGetSymbolAddress((void**)&p_h16,  g_h16);
        cudaGetSymbolAddress((void**)&p_Wh1,  g_Wh1);
        cudaGetSymbolAddress((void**)&p_Wh2,  g_Wh2);
        cudaGetSymbolAddress((void**)&p_Whg,  g_Whg);
        cudaGetSymbolAddress((void**)&p_B1,   g_B1);
        cudaGetSymbolAddress((void**)&p_B2,   g_B2);
        cudaGetSymbolAddress((void**)&p_Bg,   g_Bg);
        cudaFuncSetAttribute((const void*)gemm_h<false, 8, float>,
                             cudaFuncAttributeMaxDynamicSharedMemorySize, GEMM_SMEM_H);
        cudaFuncSetAttribute((const void*)gemm_h<false, 8, __half>,
                             cudaFuncAttributeMaxDynamicSharedMemorySize, GEMM_SMEM_H);
        cudaFuncSetAttribute((const void*)gemm_h<true, 2, __half>,
                             cudaFuncAttributeMaxDynamicSharedMemorySize, GEMM_SMEM_H);
        cudaStreamCreateWithFlags(&s1, cudaStreamNonBlocking);
        cudaEventCreateWithFlags(&evFork, cudaEventDisableTiming);
        cudaEventCreateWithFlags(&evCsr,  cudaEventDisableTiming);
    }

    const int etb  = (E + 255) / 256;
    const int nblk = (n + 255) / 256;
    const int nab  = (n * 32 + 255) / 256;      // 1 warp/node
    const int mtiles = (n + 127) / 128;

    // ---- combined packs + graph init + csr-counter zero ----
    pack_all<<<nblk, 256>>>(wq1, bq1, wk1, bk1, wv1, bv1, ws1, bs1,
                            wq2, bq2, wk2, bk2, wv2, bv2, ws2, bs2,
                            gw1, gb1, n);

    // ---- fork: CSR build on s1, concurrent with GEMM-L1 on main ----
    cudaEventRecord(evFork, 0);
    cudaStreamWaitEvent(s1, evFork, 0);
    hist<<<etb, 256, 0, s1>>>(dst, E);
    scan_blocks<<<nblk, 256, 0, s1>>>(n);
    scan_tops<<<1, 512, 0, s1>>>(nblk);
    scan_add<<<nblk, 256, 0, s1>>>(n, E);
    fill_csr<<<etb, 256, 0, s1>>>(src, dst, E);
    cudaEventRecord(evCsr, s1);

    // ---- Layer 1 GEMM (fp32 input) on main stream, overlapped with CSR ----
    gemm_h<false, 8, float><<<mtiles, 256, GEMM_SMEM_H>>>(x, n, p_Wh1, p_B1,
                                                          nullptr, nullptr, nullptr);
    cudaStreamWaitEvent(0, evCsr, 0);
    node_attn<<<nab, 256>>>(n);

    // ---- Layer 2 (fp16 input) ----
    gemm_h<false, 8, __half><<<mtiles, 256, GEMM_SMEM_H>>>(p_h16, n, p_Wh2, p_B2,
                                                           nullptr, nullptr, nullptr);
    node_attn<<<nab, 256>>>(n);

    // ---- Global attention (gate dot + exp + graph sums fused into GEMM) ----
    gemm_h<true, 2, __half><<<mtiles, 256, GEMM_SMEM_H>>>(p_h16, n, p_Whg, p_Bg,
                                                          gw2, gb2, batch);
    pool_kernel<<<(n + POOL_CHUNK - 1) / POOL_CHUNK, 128>>>(batch, n);

    // ---- Classifier ----
    classifier<<<1, 1024>>>(cw, cb, out);
}